// round 13
// baseline (speedup 1.0000x reference)
#include <cuda_runtime.h>
#include <cuda_bf16.h>
#include <cstdint>

#define NIMG 16
#define NBOX 16128
#define NCH  85
#define KSEL 500
#define KPAD 512
#define NCB  16            // 512 / 32 column blocks
#define SIG_NEG4 0.017986210f   // sigmoid(-4) for zero-overlap pairs

// ---------------- device scratch (no allocations allowed) ----------------
__device__ unsigned g_sbits[NIMG * NBOX];                 // packed score bits
__device__ float    g_s[NIMG][KPAD];                      // sorted top scores
__device__ float4   g_box[NIMG][KPAD];                    // gathered boxes
__device__ float    g_y[NIMG][KPAD];                      // gathered targets
__device__ float    g_pT[NIMG][NCB][32][KPAD];            // prune TRANSPOSED [img][cb][t][row]
__device__ float    g_E[NIMG][KPAD];                      // exp(20*v) (0 for padding)
__device__ float4   g_pair[NIMG][KPAD/2];                 // per col-pair (S, P, yS, yP)
__device__ int      g_rows[NIMG][KPAD];                   // compacted y=1 row indices
__device__ int      g_npos[NIMG];
__device__ float    g_c[NIMG][KPAD];                      // prec*y per row

__device__ __forceinline__ float frcp(float x) {
    float r; asm("rcp.approx.f32 %0, %1;" : "=f"(r) : "f"(x)); return r;
}

// ---------------- K1: scores = max over channels 1..84 ----------------
__global__ __launch_bounds__(128) void k_scores(const float* __restrict__ preds) {
    __shared__ __align__(16) float sh[128 * NCH];
    int img = blockIdx.x / 126;
    int ch  = blockIdx.x % 126;
    size_t base = ((size_t)img * NBOX + (size_t)ch * 128) * NCH;
    const float4* src = reinterpret_cast<const float4*>(preds + base);
    float4* dst = reinterpret_cast<float4*>(sh);
    #pragma unroll 8
    for (int u = threadIdx.x; u < 128 * NCH / 4; u += 128) dst[u] = src[u];
    __syncthreads();
    int r = threadIdx.x;
    float m = sh[r * NCH + 1];
    #pragma unroll
    for (int c = 2; c < NCH; ++c) m = fmaxf(m, sh[r * NCH + c]);
    g_sbits[(size_t)img * NBOX + ch * 128 + r] = __float_as_uint(m);
}

// ---------------- K2: per-image radix select (4x8-bit) + bitonic ----------------
__global__ __launch_bounds__(512) void k_select(const float4* __restrict__ boxes,
                                                const int* __restrict__ tgt) {
    const int img = blockIdx.x;
    const int tid = threadIdx.x;
    const int w = tid >> 5, lane = tid & 31;
    __shared__ unsigned whist[16 * 256];
    __shared__ unsigned hist[256];
    __shared__ unsigned wtot[16];
    __shared__ unsigned s_bin, s_rem, s_cnt;
    __shared__ unsigned long long sbuf[1024];
    const unsigned* sb = g_sbits + (size_t)img * NBOX;

    unsigned prefix = 0;
    unsigned target = KSEL;

    #pragma unroll
    for (int pass = 0; pass < 4; ++pass) {
        const int shift = 24 - pass * 8;
        for (int u = tid; u < 4096; u += 512) whist[u] = 0;
        __syncthreads();
        for (int j = tid; j < NBOX; j += 512) {
            unsigned bits = sb[j];
            bool ok = (pass == 0) || ((bits >> (shift + 8)) == prefix);
            unsigned act = __ballot_sync(0xFFFFFFFFu, ok);
            if (ok) {
                unsigned bin = (bits >> shift) & 255u;
                unsigned mask = __match_any_sync(act, bin);
                if ((mask & ((1u << lane) - 1u)) == 0)
                    whist[w * 256 + bin] += __popc(mask);
            }
        }
        __syncthreads();
        if (tid < 256) {
            unsigned h = 0;
            #pragma unroll
            for (int ww = 0; ww < 16; ++ww) h += whist[ww * 256 + tid];
            hist[tid] = h;
        }
        __syncthreads();
        unsigned x0 = (tid < 256) ? hist[255 - tid] : 0u;
        unsigned x = x0;
        #pragma unroll
        for (int off = 1; off < 32; off <<= 1) {
            unsigned yv = __shfl_up_sync(0xFFFFFFFFu, x, off);
            if (lane >= off) x += yv;
        }
        if (lane == 31) wtot[w] = x;
        __syncthreads();
        unsigned add = 0;
        #pragma unroll
        for (int ww = 0; ww < 8; ++ww) if (ww < w) add += wtot[ww];
        unsigned inc = x + add;
        if (tid < 256 && inc >= target && (inc - x0) < target) {
            s_bin = 255u - (unsigned)tid;
            s_rem = target - (inc - x0);
        }
        __syncthreads();
        prefix = (prefix << 8) | s_bin;
        target = s_rem;
        __syncthreads();
    }
    const unsigned T = prefix;

    for (int u = tid; u < 1024; u += 512) sbuf[u] = ~0ULL;
    if (tid == 0) s_cnt = 0;
    __syncthreads();
    for (int j = tid; j < NBOX; j += 512) {
        unsigned bits = sb[j];
        if (bits >= T) {
            unsigned p = atomicAdd(&s_cnt, 1);
            if (p < 1024)
                sbuf[p] = ~(((unsigned long long)bits << 32) |
                            (unsigned long long)(0xFFFFFFFFu - (unsigned)j));
        }
    }
    __syncthreads();

    for (unsigned kk = 2; kk <= 1024; kk <<= 1) {
        for (unsigned st = kk >> 1; st > 0; st >>= 1) {
            unsigned t = (unsigned)tid;
            unsigned i = ((t & ~(st - 1)) << 1) | (t & (st - 1));
            unsigned j2 = i | st;
            bool up = ((i & kk) == 0);
            unsigned long long a = sbuf[i], b = sbuf[j2];
            if ((a > b) == up) { sbuf[i] = b; sbuf[j2] = a; }
            __syncthreads();
        }
    }

    if (tid < KSEL) {
        unsigned long long key = ~sbuf[tid];
        unsigned bits = (unsigned)(key >> 32);
        unsigned idx  = 0xFFFFFFFFu - (unsigned)(key & 0xFFFFFFFFull);
        g_s[img][tid] = __uint_as_float(bits);
        g_box[img][tid] = boxes[(size_t)img * NBOX + idx];
        g_y[img][tid] = (float)tgt[(size_t)img * NBOX + idx];
    } else {
        g_s[img][tid] = 0.f;
        g_box[img][tid] = make_float4(0.f, 0.f, 0.f, 0.f);
        g_y[img][tid] = 0.f;
    }
}

// ---------------- K3: prune matrix, triangle tiles only, TRANSPOSED store ----------------
// grid (34, NIMG) x 128: 4 warps/block, one 32x32 tile per warp, 136 tiles/img.
__global__ __launch_bounds__(128) void k_prune() {
    const int img = blockIdx.y;
    const int w = threadIdx.x >> 5, lane = threadIdx.x & 31;
    const int t = blockIdx.x * 4 + w;                 // tile id, 0..135
    __shared__ float4 sbj[4][32];
    __shared__ float  saj[4][32];

    int rb = (int)((sqrtf(8.f * (float)t + 1.f) - 1.f) * 0.5f);
    if ((rb + 1) * (rb + 2) / 2 <= t) rb++;
    if (rb * (rb + 1) / 2 > t) rb--;
    const int cb = t - rb * (rb + 1) / 2;

    {
        float4 b = g_box[img][cb * 32 + lane];
        sbj[w][lane] = b;
        saj[w][lane] = fmaxf(b.z - b.x, 0.f) * fmaxf(b.w - b.y, 0.f);
    }
    __syncwarp();

    const int i = rb * 32 + lane;
    float4 bi = g_box[img][i];
    float ai = fmaxf(bi.z - bi.x, 0.f) * fmaxf(bi.w - bi.y, 0.f);
    #pragma unroll
    for (int c = 0; c < 32; ++c) {
        float4 bb = sbj[w][c];
        float iw = fminf(bi.z, bb.z) - fmaxf(bi.x, bb.x);
        float ih = fminf(bi.w, bb.w) - fmaxf(bi.y, bb.y);
        bool ov = (iw > 0.f) && (ih > 0.f);
        float p;
        if (__any_sync(0xFFFFFFFFu, ov)) {
            float inter = fmaxf(iw, 0.f) * fmaxf(ih, 0.f);
            float uni = ai + saj[w][c] - inter;
            float iou = inter * frcp(fmaxf(uni, 1e-9f));
            p = frcp(1.f + __expf((0.4f - iou) * 10.f));
        } else {
            p = SIG_NEG4;
        }
        g_pT[img][cb][c][i] = p;      // transposed: coalesced across lanes
    }
}

// ---------------- K4: soft-NMS — R10 body with 4-col shfl-round diag solve ----------------
__global__ __launch_bounds__(512) void k_nms() {
    const int img = blockIdx.x;
    const int tid = threadIdx.x;
    const int w = tid >> 5, lane = tid & 31;
    __shared__ __align__(16) float vsh[KPAD];
    __shared__ int wcnt[NCB];
    const float* pT = &g_pT[img][0][0][0];       // [cb][t][row], row stride KPAD

    float cur[32], nxt[32];
    #pragma unroll
    for (int u = 0; u < 32; ++u) cur[u] = pT[u * KPAD + tid];   // tile 0, coalesced

    float s = g_s[img][tid];
    float acc = 0.f;
    for (int cb = 0; cb < NCB; ++cb) {
        if (cb < NCB - 1 && w >= cb + 1) {       // prefetch next tile (coalesced scalar LDGs)
            const float* nb = pT + (size_t)(cb + 1) * 32 * KPAD;
            #pragma unroll
            for (int u = 0; u < 32; ++u) nxt[u] = nb[u * KPAD + tid];
        }
        if (w == cb) {
            // diag solve: 8 rounds of 4 columns; triangle entries shfl'd from
            // owning lanes' registers (static indices), v0..v3 computed
            // redundantly on all lanes, unconditional rr update.
            float rr = s - acc;
            #pragma unroll
            for (int q = 0; q < 8; ++q) {
                const int m0 = q * 4;
                float a0 = __shfl_sync(0xFFFFFFFFu, rr, m0 + 0);
                float a1 = __shfl_sync(0xFFFFFFFFu, rr, m0 + 1);
                float a2 = __shfl_sync(0xFFFFFFFFu, rr, m0 + 2);
                float a3 = __shfl_sync(0xFFFFFFFFu, rr, m0 + 3);
                float p10 = __shfl_sync(0xFFFFFFFFu, cur[m0 + 0], m0 + 1);
                float p20 = __shfl_sync(0xFFFFFFFFu, cur[m0 + 0], m0 + 2);
                float p21 = __shfl_sync(0xFFFFFFFFu, cur[m0 + 1], m0 + 2);
                float p30 = __shfl_sync(0xFFFFFFFFu, cur[m0 + 0], m0 + 3);
                float p31 = __shfl_sync(0xFFFFFFFFu, cur[m0 + 1], m0 + 3);
                float p32 = __shfl_sync(0xFFFFFFFFu, cur[m0 + 2], m0 + 3);
                float v0 = fmaxf(a0, 0.f);
                float v1 = fmaxf(fmaf(-p10, v0, a1), 0.f);
                float v2 = fmaxf(fmaf(-p21, v1, fmaf(-p20, v0, a2)), 0.f);
                float v3 = fmaxf(fmaf(-p32, v2,
                                fmaf(-p31, v1, fmaf(-p30, v0, a3))), 0.f);
                if (lane == m0 + 0) vsh[tid] = v0;
                if (lane == m0 + 1) vsh[tid] = v1;
                if (lane == m0 + 2) vsh[tid] = v2;
                if (lane == m0 + 3) vsh[tid] = v3;
                float t01 = fmaf(cur[m0 + 1], v1, cur[m0 + 0] * v0);
                float t23 = fmaf(cur[m0 + 3], v3, cur[m0 + 2] * v2);
                rr = rr - (t01 + t23);
            }
        }
        __syncthreads();
        if (w > cb) {
            const float4* vv = reinterpret_cast<const float4*>(&vsh[cb * 32]);
            #pragma unroll
            for (int u = 0; u < 8; ++u) {
                float4 v4 = vv[u];
                acc = fmaf(cur[4*u+0], v4.x, acc);
                acc = fmaf(cur[4*u+1], v4.y, acc);
                acc = fmaf(cur[4*u+2], v4.z, acc);
                acc = fmaf(cur[4*u+3], v4.w, acc);
            }
        }
        #pragma unroll
        for (int u = 0; u < 32; ++u) cur[u] = nxt[u];
    }
    __syncthreads();

    // ---- epilogue: E, pair constants, positive-row compaction ----
    float v = vsh[tid];
    bool valid = tid < KSEL;
    float E = valid ? __expf(20.f * v) : 0.f;
    float y = valid ? g_y[img][tid] : 0.f;
    g_E[img][tid] = E;
    g_c[img][tid] = 0.f;

    float Eb = __shfl_down_sync(0xFFFFFFFFu, E, 1);
    float yb = __shfl_down_sync(0xFFFFFFFFu, y, 1);
    if (!(lane & 1)) {
        float S = E + Eb;
        float P = E * Eb;
        float yS = fmaf(y, E, yb * Eb);
        float yP = (y + yb) * P;
        g_pair[img][tid >> 1] = make_float4(S, P, yS, yP);
    }

    bool pos = valid && (y != 0.f);
    unsigned vote = __ballot_sync(0xFFFFFFFFu, pos);
    if (lane == 0) wcnt[w] = __popc(vote);
    __syncthreads();
    int base = 0;
    #pragma unroll
    for (int ww = 0; ww < NCB; ++ww) if (ww < w) base += wcnt[ww];
    if (pos) {
        int off = __popc(vote & ((1u << lane) - 1u));
        g_rows[img][base + off] = tid;
    }
    if (tid == 0) {
        int tot = 0;
        #pragma unroll
        for (int ww = 0; ww < NCB; ++ww) tot += wcnt[ww];
        g_npos[img] = tot;
    }
}

// ---------------- K5: ap_loss — one warp per positive row, paired columns ----------------
// h_ia + h_ib = (Ei*S + 2P) / (Ei^2 + Ei*S + P): 1 rcp per 2 columns (exact algebra)
__global__ __launch_bounds__(256) void k_ap() {
    const int img = blockIdx.y;
    const int wid = threadIdx.x >> 5, lane = threadIdx.x & 31;
    const int slot = blockIdx.x * 8 + wid;
    if (slot >= g_npos[img]) return;     // uniform per warp
    const int i = g_rows[img][slot];
    const float Ei = g_E[img][i];
    const float4* pr = g_pair[img];
    float sh = 0.f, shy = 0.f;
    #pragma unroll
    for (int u = 0; u < 8; ++u) {
        float4 q = pr[u * 32 + lane];
        float t = fmaf(Ei, q.x, q.y);       // Ei*S + P
        float num = t + q.y;                // Ei*S + 2P
        float den = fmaf(Ei, Ei, t);        // Ei^2 + Ei*S + P
        float rr = frcp(den);
        sh = fmaf(num, rr, sh);
        float numy = fmaf(Ei, q.z, q.w);    // Ei*yS + yP
        shy = fmaf(numy, rr, shy);
    }
    #pragma unroll
    for (int off = 16; off > 0; off >>= 1) {
        sh  += __shfl_down_sync(0xFFFFFFFFu, sh, off);
        shy += __shfl_down_sync(0xFFFFFFFFu, shy, off);
    }
    // sums include self-pair exactly as h_ii = 0.5
    if (lane == 0) g_c[img][i] = __fdividef(0.5f + shy, 0.5f + sh);
}

// ---------------- K6: warp-per-image final reduction ----------------
__global__ __launch_bounds__(512) void k_final(float* __restrict__ out) {
    const int w = threadIdx.x >> 5, lane = threadIdx.x & 31;
    __shared__ float part[16];
    float sc = 0.f, sy = 0.f;
    #pragma unroll
    for (int u = lane; u < KPAD; u += 32) {
        sc += g_c[w][u];
        sy += g_y[w][u];
    }
    #pragma unroll
    for (int off = 16; off > 0; off >>= 1) {
        sc += __shfl_down_sync(0xFFFFFFFFu, sc, off);
        sy += __shfl_down_sync(0xFFFFFFFFu, sy, off);
    }
    if (lane == 0) part[w] = 1.f - sc / fmaxf(sy, 1.f);
    __syncthreads();
    if (threadIdx.x == 0) {
        float t = 0.f;
        #pragma unroll
        for (int k = 0; k < NIMG; ++k) t += part[k];
        out[0] = t / (float)NIMG;
    }
}

// ---------------- driver ----------------
extern "C" void kernel_launch(void* const* d_in, const int* in_sizes, int n_in,
                              void* d_out, int out_size) {
    const float* preds = nullptr;
    const float* boxes = nullptr;
    const int*   targets = nullptr;
    for (int i = 0; i < n_in; ++i) {
        long sz = in_sizes[i];
        if (sz == (long)NIMG * NBOX * NCH) preds = (const float*)d_in[i];
        else if (sz == (long)NIMG * NBOX * 4) boxes = (const float*)d_in[i];
        else if (sz == (long)NIMG * NBOX) targets = (const int*)d_in[i];
    }
    if (!preds)   preds   = (const float*)d_in[0];
    if (!boxes)   boxes   = (const float*)d_in[1];
    if (!targets) targets = (const int*)d_in[2];

    k_scores<<<NIMG * 126, 128>>>(preds);
    k_select<<<NIMG, 512>>>(reinterpret_cast<const float4*>(boxes), targets);
    k_prune<<<dim3(34, NIMG), 128>>>();
    k_nms<<<NIMG, 512>>>();
    k_ap<<<dim3(64, NIMG), 256>>>();
    k_final<<<1, 512>>>((float*)d_out);
}

// round 14
// speedup vs baseline: 1.5186x; 1.5186x over previous
#include <cuda_runtime.h>
#include <cuda_bf16.h>
#include <cstdint>

#define NIMG 16
#define NBOX 16128
#define NCH  85
#define KSEL 500
#define KPAD 512
#define NCB  16            // 512 / 32 column blocks
#define SIG_NEG4 0.017986210f   // sigmoid(-4) for zero-overlap pairs

#define BAR_SYNC(id,cnt)   asm volatile("bar.sync %0, %1;"   :: "r"(id), "r"(cnt) : "memory")
#define BAR_ARRIVE(id,cnt) asm volatile("bar.arrive %0, %1;" :: "r"(id), "r"(cnt) : "memory")

// ---------------- device scratch (no allocations allowed) ----------------
__device__ unsigned g_sbits[NIMG * NBOX];                 // packed score bits
__device__ float    g_s[NIMG][KPAD];                      // sorted top scores
__device__ float4   g_box[NIMG][KPAD];                    // gathered boxes
__device__ float    g_y[NIMG][KPAD];                      // gathered targets
__device__ float    g_pT[NIMG][NCB][32][KPAD];            // prune TRANSPOSED [img][cb][t][row]
__device__ float    g_E[NIMG][KPAD];                      // exp(20*v) (0 for padding)
__device__ float4   g_pair[NIMG][KPAD/2];                 // per col-pair (S, P, yS, yP)
__device__ int      g_rows[NIMG][KPAD];                   // compacted y=1 row indices
__device__ int      g_npos[NIMG];
__device__ float    g_c[NIMG][KPAD];                      // prec*y per row

__device__ __forceinline__ float frcp(float x) {
    float r; asm("rcp.approx.f32 %0, %1;" : "=f"(r) : "f"(x)); return r;
}

// ---------------- K1: scores = max over channels 1..84 ----------------
__global__ __launch_bounds__(128) void k_scores(const float* __restrict__ preds) {
    __shared__ __align__(16) float sh[128 * NCH];
    int img = blockIdx.x / 126;
    int ch  = blockIdx.x % 126;
    size_t base = ((size_t)img * NBOX + (size_t)ch * 128) * NCH;
    const float4* src = reinterpret_cast<const float4*>(preds + base);
    float4* dst = reinterpret_cast<float4*>(sh);
    #pragma unroll 8
    for (int u = threadIdx.x; u < 128 * NCH / 4; u += 128) dst[u] = src[u];
    __syncthreads();
    int r = threadIdx.x;
    float m = sh[r * NCH + 1];
    #pragma unroll
    for (int c = 2; c < NCH; ++c) m = fmaxf(m, sh[r * NCH + c]);
    g_sbits[(size_t)img * NBOX + ch * 128 + r] = __float_as_uint(m);
}

// ---------------- K2: per-image radix select (4x8-bit) + bitonic ----------------
__global__ __launch_bounds__(512) void k_select(const float4* __restrict__ boxes,
                                                const int* __restrict__ tgt) {
    const int img = blockIdx.x;
    const int tid = threadIdx.x;
    const int w = tid >> 5, lane = tid & 31;
    __shared__ unsigned whist[16 * 256];
    __shared__ unsigned hist[256];
    __shared__ unsigned wtot[16];
    __shared__ unsigned s_bin, s_rem, s_cnt;
    __shared__ unsigned long long sbuf[1024];
    const unsigned* sb = g_sbits + (size_t)img * NBOX;

    unsigned prefix = 0;
    unsigned target = KSEL;

    #pragma unroll
    for (int pass = 0; pass < 4; ++pass) {
        const int shift = 24 - pass * 8;
        for (int u = tid; u < 4096; u += 512) whist[u] = 0;
        __syncthreads();
        for (int j = tid; j < NBOX; j += 512) {
            unsigned bits = sb[j];
            bool ok = (pass == 0) || ((bits >> (shift + 8)) == prefix);
            unsigned act = __ballot_sync(0xFFFFFFFFu, ok);
            if (ok) {
                unsigned bin = (bits >> shift) & 255u;
                unsigned mask = __match_any_sync(act, bin);
                if ((mask & ((1u << lane) - 1u)) == 0)
                    whist[w * 256 + bin] += __popc(mask);
            }
        }
        __syncthreads();
        if (tid < 256) {
            unsigned h = 0;
            #pragma unroll
            for (int ww = 0; ww < 16; ++ww) h += whist[ww * 256 + tid];
            hist[tid] = h;
        }
        __syncthreads();
        unsigned x0 = (tid < 256) ? hist[255 - tid] : 0u;
        unsigned x = x0;
        #pragma unroll
        for (int off = 1; off < 32; off <<= 1) {
            unsigned yv = __shfl_up_sync(0xFFFFFFFFu, x, off);
            if (lane >= off) x += yv;
        }
        if (lane == 31) wtot[w] = x;
        __syncthreads();
        unsigned add = 0;
        #pragma unroll
        for (int ww = 0; ww < 8; ++ww) if (ww < w) add += wtot[ww];
        unsigned inc = x + add;
        if (tid < 256 && inc >= target && (inc - x0) < target) {
            s_bin = 255u - (unsigned)tid;
            s_rem = target - (inc - x0);
        }
        __syncthreads();
        prefix = (prefix << 8) | s_bin;
        target = s_rem;
        __syncthreads();
    }
    const unsigned T = prefix;

    for (int u = tid; u < 1024; u += 512) sbuf[u] = ~0ULL;
    if (tid == 0) s_cnt = 0;
    __syncthreads();
    for (int j = tid; j < NBOX; j += 512) {
        unsigned bits = sb[j];
        if (bits >= T) {
            unsigned p = atomicAdd(&s_cnt, 1);
            if (p < 1024)
                sbuf[p] = ~(((unsigned long long)bits << 32) |
                            (unsigned long long)(0xFFFFFFFFu - (unsigned)j));
        }
    }
    __syncthreads();

    for (unsigned kk = 2; kk <= 1024; kk <<= 1) {
        for (unsigned st = kk >> 1; st > 0; st >>= 1) {
            unsigned t = (unsigned)tid;
            unsigned i = ((t & ~(st - 1)) << 1) | (t & (st - 1));
            unsigned j2 = i | st;
            bool up = ((i & kk) == 0);
            unsigned long long a = sbuf[i], b = sbuf[j2];
            if ((a > b) == up) { sbuf[i] = b; sbuf[j2] = a; }
            __syncthreads();
        }
    }

    if (tid < KSEL) {
        unsigned long long key = ~sbuf[tid];
        unsigned bits = (unsigned)(key >> 32);
        unsigned idx  = 0xFFFFFFFFu - (unsigned)(key & 0xFFFFFFFFull);
        g_s[img][tid] = __uint_as_float(bits);
        g_box[img][tid] = boxes[(size_t)img * NBOX + idx];
        g_y[img][tid] = (float)tgt[(size_t)img * NBOX + idx];
    } else {
        g_s[img][tid] = 0.f;
        g_box[img][tid] = make_float4(0.f, 0.f, 0.f, 0.f);
        g_y[img][tid] = 0.f;
    }
}

// ---------------- K3: prune matrix, triangle tiles only, TRANSPOSED store ----------------
// grid (34, NIMG) x 128: 4 warps/block, one 32x32 tile per warp, 136 tiles/img.
__global__ __launch_bounds__(128) void k_prune() {
    const int img = blockIdx.y;
    const int w = threadIdx.x >> 5, lane = threadIdx.x & 31;
    const int t = blockIdx.x * 4 + w;                 // tile id, 0..135
    __shared__ float4 sbj[4][32];
    __shared__ float  saj[4][32];

    int rb = (int)((sqrtf(8.f * (float)t + 1.f) - 1.f) * 0.5f);
    if ((rb + 1) * (rb + 2) / 2 <= t) rb++;
    if (rb * (rb + 1) / 2 > t) rb--;
    const int cb = t - rb * (rb + 1) / 2;

    {
        float4 b = g_box[img][cb * 32 + lane];
        sbj[w][lane] = b;
        saj[w][lane] = fmaxf(b.z - b.x, 0.f) * fmaxf(b.w - b.y, 0.f);
    }
    __syncwarp();

    const int i = rb * 32 + lane;
    float4 bi = g_box[img][i];
    float ai = fmaxf(bi.z - bi.x, 0.f) * fmaxf(bi.w - bi.y, 0.f);
    #pragma unroll
    for (int c = 0; c < 32; ++c) {
        float4 bb = sbj[w][c];
        float iw = fminf(bi.z, bb.z) - fmaxf(bi.x, bb.x);
        float ih = fminf(bi.w, bb.w) - fmaxf(bi.y, bb.y);
        bool ov = (iw > 0.f) && (ih > 0.f);
        float p;
        if (__any_sync(0xFFFFFFFFu, ov)) {
            float inter = fmaxf(iw, 0.f) * fmaxf(ih, 0.f);
            float uni = ai + saj[w][c] - inter;
            float iou = inter * frcp(fmaxf(uni, 1e-9f));
            p = frcp(1.f + __expf((0.4f - iou) * 10.f));
        } else {
            p = SIG_NEG4;
        }
        g_pT[img][cb][c][i] = p;      // transposed: coalesced across lanes
    }
}

// ---------------- K4: soft-NMS — R10 loads+diag solve, named-barrier dataflow ----------------
// Stage cb uses named barrier id (cb+1), count (NCB-cb)*32: producer warp cb
// arrives after publishing vsh; consumer warps > cb sync. __syncthreads (bar 0)
// appears only in the epilogue -> no ID collision.
__global__ __launch_bounds__(512) void k_nms() {
    const int img = blockIdx.x;
    const int tid = threadIdx.x;
    const int w = tid >> 5, lane = tid & 31;
    __shared__ __align__(16) float vsh[KPAD];
    __shared__ int wcnt[NCB];
    const float* pT = &g_pT[img][0][0][0];       // [cb][t][row], row stride KPAD

    float cur[32], nxt[32];
    #pragma unroll
    for (int u = 0; u < 32; ++u) cur[u] = pT[u * KPAD + tid];   // tile 0, coalesced

    float s = g_s[img][tid];
    float acc = 0.f;

    // consume stages 0..w-1 as they become available
    for (int cb = 0; cb < w; ++cb) {
        const float* nb = pT + (size_t)(cb + 1) * 32 * KPAD;    // prefetch (not gated)
        #pragma unroll
        for (int u = 0; u < 32; ++u) nxt[u] = nb[u * KPAD + tid];

        BAR_SYNC(cb + 1, (NCB - cb) * 32);        // wait for v[cb*32 .. +31]

        const float4* vv = reinterpret_cast<const float4*>(&vsh[cb * 32]);
        #pragma unroll
        for (int u = 0; u < 8; ++u) {
            float4 v4 = vv[u];
            acc = fmaf(cur[4*u+0], v4.x, acc);
            acc = fmaf(cur[4*u+1], v4.y, acc);
            acc = fmaf(cur[4*u+2], v4.z, acc);
            acc = fmaf(cur[4*u+3], v4.w, acc);
        }
        #pragma unroll
        for (int u = 0; u < 32; ++u) cur[u] = nxt[u];
    }

    // own diagonal: serial 32-col shfl chain (R10 pattern, frozen)
    float vown;
    {
        float rr = s - acc;
        #pragma unroll
        for (int m = 0; m < 32; ++m) {
            float vm = __shfl_sync(0xFFFFFFFFu, fmaxf(rr, 0.f), m);
            if (lane == m) { vsh[tid] = vm; vown = vm; }
            if (lane > m) rr = fmaf(-cur[m], vm, rr);
        }
    }
    __threadfence_block();                        // STS of vsh visible
    if (w < NCB - 1) BAR_ARRIVE(w + 1, (NCB - w) * 32);

    // ---- epilogue: E, pair constants, positive-row compaction ----
    float v = vown;
    bool valid = tid < KSEL;
    float E = valid ? __expf(20.f * v) : 0.f;
    float y = valid ? g_y[img][tid] : 0.f;
    g_E[img][tid] = E;
    g_c[img][tid] = 0.f;

    float Eb = __shfl_down_sync(0xFFFFFFFFu, E, 1);
    float yb = __shfl_down_sync(0xFFFFFFFFu, y, 1);
    if (!(lane & 1)) {
        float S = E + Eb;
        float P = E * Eb;
        float yS = fmaf(y, E, yb * Eb);
        float yP = (y + yb) * P;
        g_pair[img][tid >> 1] = make_float4(S, P, yS, yP);
    }

    bool pos = valid && (y != 0.f);
    unsigned vote = __ballot_sync(0xFFFFFFFFu, pos);
    if (lane == 0) wcnt[w] = __popc(vote);
    __syncthreads();
    int base = 0;
    #pragma unroll
    for (int ww = 0; ww < NCB; ++ww) if (ww < w) base += wcnt[ww];
    if (pos) {
        int off = __popc(vote & ((1u << lane) - 1u));
        g_rows[img][base + off] = tid;
    }
    if (tid == 0) {
        int tot = 0;
        #pragma unroll
        for (int ww = 0; ww < NCB; ++ww) tot += wcnt[ww];
        g_npos[img] = tot;
    }
}

// ---------------- K5: ap_loss — one warp per positive row, paired columns ----------------
// h_ia + h_ib = (Ei*S + 2P) / (Ei^2 + Ei*S + P): 1 rcp per 2 columns (exact algebra)
__global__ __launch_bounds__(256) void k_ap() {
    const int img = blockIdx.y;
    const int wid = threadIdx.x >> 5, lane = threadIdx.x & 31;
    const int slot = blockIdx.x * 8 + wid;
    if (slot >= g_npos[img]) return;     // uniform per warp
    const int i = g_rows[img][slot];
    const float Ei = g_E[img][i];
    const float4* pr = g_pair[img];
    float sh = 0.f, shy = 0.f;
    #pragma unroll
    for (int u = 0; u < 8; ++u) {
        float4 q = pr[u * 32 + lane];
        float t = fmaf(Ei, q.x, q.y);       // Ei*S + P
        float num = t + q.y;                // Ei*S + 2P
        float den = fmaf(Ei, Ei, t);        // Ei^2 + Ei*S + P
        float rr = frcp(den);
        sh = fmaf(num, rr, sh);
        float numy = fmaf(Ei, q.z, q.w);    // Ei*yS + yP
        shy = fmaf(numy, rr, shy);
    }
    #pragma unroll
    for (int off = 16; off > 0; off >>= 1) {
        sh  += __shfl_down_sync(0xFFFFFFFFu, sh, off);
        shy += __shfl_down_sync(0xFFFFFFFFu, shy, off);
    }
    // sums include self-pair exactly as h_ii = 0.5
    if (lane == 0) g_c[img][i] = __fdividef(0.5f + shy, 0.5f + sh);
}

// ---------------- K6: warp-per-image final reduction ----------------
__global__ __launch_bounds__(512) void k_final(float* __restrict__ out) {
    const int w = threadIdx.x >> 5, lane = threadIdx.x & 31;
    __shared__ float part[16];
    float sc = 0.f, sy = 0.f;
    #pragma unroll
    for (int u = lane; u < KPAD; u += 32) {
        sc += g_c[w][u];
        sy += g_y[w][u];
    }
    #pragma unroll
    for (int off = 16; off > 0; off >>= 1) {
        sc += __shfl_down_sync(0xFFFFFFFFu, sc, off);
        sy += __shfl_down_sync(0xFFFFFFFFu, sy, off);
    }
    if (lane == 0) part[w] = 1.f - sc / fmaxf(sy, 1.f);
    __syncthreads();
    if (threadIdx.x == 0) {
        float t = 0.f;
        #pragma unroll
        for (int k = 0; k < NIMG; ++k) t += part[k];
        out[0] = t / (float)NIMG;
    }
}

// ---------------- driver ----------------
extern "C" void kernel_launch(void* const* d_in, const int* in_sizes, int n_in,
                              void* d_out, int out_size) {
    const float* preds = nullptr;
    const float* boxes = nullptr;
    const int*   targets = nullptr;
    for (int i = 0; i < n_in; ++i) {
        long sz = in_sizes[i];
        if (sz == (long)NIMG * NBOX * NCH) preds = (const float*)d_in[i];
        else if (sz == (long)NIMG * NBOX * 4) boxes = (const float*)d_in[i];
        else if (sz == (long)NIMG * NBOX) targets = (const int*)d_in[i];
    }
    if (!preds)   preds   = (const float*)d_in[0];
    if (!boxes)   boxes   = (const float*)d_in[1];
    if (!targets) targets = (const int*)d_in[2];

    k_scores<<<NIMG * 126, 128>>>(preds);
    k_select<<<NIMG, 512>>>(reinterpret_cast<const float4*>(boxes), targets);
    k_prune<<<dim3(34, NIMG), 128>>>();
    k_nms<<<NIMG, 512>>>();
    k_ap<<<dim3(64, NIMG), 256>>>();
    k_final<<<1, 512>>>((float*)d_out);
}

// round 15
// speedup vs baseline: 1.5554x; 1.0242x over previous
#include <cuda_runtime.h>
#include <cuda_bf16.h>
#include <cstdint>

#define NIMG 16
#define NBOX 16128
#define NCH  85
#define KSEL 500
#define KPAD 512
#define NCB  16            // 512 / 32 column blocks
#define SIG_NEG4 0.017986210f   // sigmoid(-4) for zero-overlap pairs

#define BAR_SYNC(id,cnt)   asm volatile("bar.sync %0, %1;"   :: "r"(id), "r"(cnt) : "memory")
#define BAR_ARRIVE(id,cnt) asm volatile("bar.arrive %0, %1;" :: "r"(id), "r"(cnt) : "memory")

// ---------------- device scratch (no allocations allowed) ----------------
__device__ unsigned g_sbits[NIMG * NBOX];                 // packed score bits
__device__ float    g_s[NIMG][KPAD];                      // sorted top scores
__device__ float4   g_box[NIMG][KPAD];                    // gathered boxes
__device__ float    g_y[NIMG][KPAD];                      // gathered targets
__device__ float    g_pT[NIMG][NCB][32][KPAD];            // prune TRANSPOSED [img][cb][t][row]
__device__ float    g_E[NIMG][KPAD];                      // exp(20*v) (0 for padding)
__device__ float4   g_pair[NIMG][KPAD/2];                 // per col-pair (S, P, yS, yP)
__device__ int      g_rows[NIMG][KPAD];                   // compacted y=1 row indices
__device__ int      g_npos[NIMG];
__device__ float    g_c[NIMG][KPAD];                      // prec*y per row

__device__ __forceinline__ float frcp(float x) {
    float r; asm("rcp.approx.f32 %0, %1;" : "=f"(r) : "f"(x)); return r;
}

// ---------------- K1: scores = max over channels 1..84 ----------------
__global__ __launch_bounds__(128) void k_scores(const float* __restrict__ preds) {
    __shared__ __align__(16) float sh[128 * NCH];
    int img = blockIdx.x / 126;
    int ch  = blockIdx.x % 126;
    size_t base = ((size_t)img * NBOX + (size_t)ch * 128) * NCH;
    const float4* src = reinterpret_cast<const float4*>(preds + base);
    float4* dst = reinterpret_cast<float4*>(sh);
    #pragma unroll 8
    for (int u = threadIdx.x; u < 128 * NCH / 4; u += 128) dst[u] = src[u];
    __syncthreads();
    int r = threadIdx.x;
    float m = sh[r * NCH + 1];
    #pragma unroll
    for (int c = 2; c < NCH; ++c) m = fmaxf(m, sh[r * NCH + c]);
    g_sbits[(size_t)img * NBOX + ch * 128 + r] = __float_as_uint(m);
}

// ---------------- K2: per-image radix select (3x8-bit) + gather + bitonic ----------------
// 3 passes resolve a 24-bit prefix; gather everything with bits >= prefix<<8
// (500 + in-bin extras, ~540 expected, buffer 1024); exact sort + cut at 500.
__global__ __launch_bounds__(512) void k_select(const float4* __restrict__ boxes,
                                                const int* __restrict__ tgt) {
    const int img = blockIdx.x;
    const int tid = threadIdx.x;
    const int w = tid >> 5, lane = tid & 31;
    __shared__ unsigned whist[16 * 256];
    __shared__ unsigned hist[256];
    __shared__ unsigned wtot[16];
    __shared__ unsigned s_bin, s_rem, s_cnt;
    __shared__ unsigned long long sbuf[1024];
    const unsigned* sb = g_sbits + (size_t)img * NBOX;

    unsigned prefix = 0;
    unsigned target = KSEL;

    #pragma unroll
    for (int pass = 0; pass < 3; ++pass) {
        const int shift = 24 - pass * 8;
        for (int u = tid; u < 4096; u += 512) whist[u] = 0;
        __syncthreads();
        for (int j = tid; j < NBOX; j += 512) {
            unsigned bits = sb[j];
            bool ok = (pass == 0) || ((bits >> (shift + 8)) == prefix);
            unsigned act = __ballot_sync(0xFFFFFFFFu, ok);
            if (ok) {
                unsigned bin = (bits >> shift) & 255u;
                unsigned mask = __match_any_sync(act, bin);
                if ((mask & ((1u << lane) - 1u)) == 0)
                    whist[w * 256 + bin] += __popc(mask);
            }
        }
        __syncthreads();
        if (tid < 256) {
            unsigned h = 0;
            #pragma unroll
            for (int ww = 0; ww < 16; ++ww) h += whist[ww * 256 + tid];
            hist[tid] = h;
        }
        __syncthreads();
        unsigned x0 = (tid < 256) ? hist[255 - tid] : 0u;
        unsigned x = x0;
        #pragma unroll
        for (int off = 1; off < 32; off <<= 1) {
            unsigned yv = __shfl_up_sync(0xFFFFFFFFu, x, off);
            if (lane >= off) x += yv;
        }
        if (lane == 31) wtot[w] = x;
        __syncthreads();
        unsigned add = 0;
        #pragma unroll
        for (int ww = 0; ww < 8; ++ww) if (ww < w) add += wtot[ww];
        unsigned inc = x + add;
        if (tid < 256 && inc >= target && (inc - x0) < target) {
            s_bin = 255u - (unsigned)tid;
            s_rem = target - (inc - x0);
        }
        __syncthreads();
        prefix = (prefix << 8) | s_bin;
        target = s_rem;
        __syncthreads();
    }
    const unsigned T = prefix << 8;      // 24-bit threshold; superset gather

    for (int u = tid; u < 1024; u += 512) sbuf[u] = ~0ULL;
    if (tid == 0) s_cnt = 0;
    __syncthreads();
    for (int j = tid; j < NBOX; j += 512) {
        unsigned bits = sb[j];
        if (bits >= T) {
            unsigned p = atomicAdd(&s_cnt, 1);
            if (p < 1024)
                sbuf[p] = ~(((unsigned long long)bits << 32) |
                            (unsigned long long)(0xFFFFFFFFu - (unsigned)j));
        }
    }
    __syncthreads();

    for (unsigned kk = 2; kk <= 1024; kk <<= 1) {
        for (unsigned st = kk >> 1; st > 0; st >>= 1) {
            unsigned t = (unsigned)tid;
            unsigned i = ((t & ~(st - 1)) << 1) | (t & (st - 1));
            unsigned j2 = i | st;
            bool up = ((i & kk) == 0);
            unsigned long long a = sbuf[i], b = sbuf[j2];
            if ((a > b) == up) { sbuf[i] = b; sbuf[j2] = a; }
            __syncthreads();
        }
    }

    if (tid < KSEL) {
        unsigned long long key = ~sbuf[tid];
        unsigned bits = (unsigned)(key >> 32);
        unsigned idx  = 0xFFFFFFFFu - (unsigned)(key & 0xFFFFFFFFull);
        g_s[img][tid] = __uint_as_float(bits);
        g_box[img][tid] = boxes[(size_t)img * NBOX + idx];
        g_y[img][tid] = (float)tgt[(size_t)img * NBOX + idx];
    } else {
        g_s[img][tid] = 0.f;
        g_box[img][tid] = make_float4(0.f, 0.f, 0.f, 0.f);
        g_y[img][tid] = 0.f;
    }
}

// ---------------- K3: prune matrix, triangle tiles only, TRANSPOSED store ----------------
// grid (34, NIMG) x 128: 4 warps/block, one 32x32 tile per warp, 136 tiles/img.
__global__ __launch_bounds__(128) void k_prune() {
    const int img = blockIdx.y;
    const int w = threadIdx.x >> 5, lane = threadIdx.x & 31;
    const int t = blockIdx.x * 4 + w;                 // tile id, 0..135
    __shared__ float4 sbj[4][32];
    __shared__ float  saj[4][32];

    int rb = (int)((sqrtf(8.f * (float)t + 1.f) - 1.f) * 0.5f);
    if ((rb + 1) * (rb + 2) / 2 <= t) rb++;
    if (rb * (rb + 1) / 2 > t) rb--;
    const int cb = t - rb * (rb + 1) / 2;

    {
        float4 b = g_box[img][cb * 32 + lane];
        sbj[w][lane] = b;
        saj[w][lane] = fmaxf(b.z - b.x, 0.f) * fmaxf(b.w - b.y, 0.f);
    }
    __syncwarp();

    const int i = rb * 32 + lane;
    float4 bi = g_box[img][i];
    float ai = fmaxf(bi.z - bi.x, 0.f) * fmaxf(bi.w - bi.y, 0.f);
    #pragma unroll
    for (int c = 0; c < 32; ++c) {
        float4 bb = sbj[w][c];
        float iw = fminf(bi.z, bb.z) - fmaxf(bi.x, bb.x);
        float ih = fminf(bi.w, bb.w) - fmaxf(bi.y, bb.y);
        bool ov = (iw > 0.f) && (ih > 0.f);
        float p;
        if (__any_sync(0xFFFFFFFFu, ov)) {
            float inter = fmaxf(iw, 0.f) * fmaxf(ih, 0.f);
            float uni = ai + saj[w][c] - inter;
            float iou = inter * frcp(fmaxf(uni, 1e-9f));
            p = frcp(1.f + __expf((0.4f - iou) * 10.f));
        } else {
            p = SIG_NEG4;
        }
        g_pT[img][cb][c][i] = p;      // transposed: coalesced across lanes
    }
}

// ---------------- K4: soft-NMS — R14 (named-barrier dataflow, frozen) ----------------
__global__ __launch_bounds__(512) void k_nms() {
    const int img = blockIdx.x;
    const int tid = threadIdx.x;
    const int w = tid >> 5, lane = tid & 31;
    __shared__ __align__(16) float vsh[KPAD];
    __shared__ int wcnt[NCB];
    const float* pT = &g_pT[img][0][0][0];       // [cb][t][row], row stride KPAD

    float cur[32], nxt[32];
    #pragma unroll
    for (int u = 0; u < 32; ++u) cur[u] = pT[u * KPAD + tid];   // tile 0, coalesced

    float s = g_s[img][tid];
    float acc = 0.f;

    // consume stages 0..w-1 as they become available
    for (int cb = 0; cb < w; ++cb) {
        const float* nb = pT + (size_t)(cb + 1) * 32 * KPAD;    // prefetch (not gated)
        #pragma unroll
        for (int u = 0; u < 32; ++u) nxt[u] = nb[u * KPAD + tid];

        BAR_SYNC(cb + 1, (NCB - cb) * 32);        // wait for v[cb*32 .. +31]

        const float4* vv = reinterpret_cast<const float4*>(&vsh[cb * 32]);
        #pragma unroll
        for (int u = 0; u < 8; ++u) {
            float4 v4 = vv[u];
            acc = fmaf(cur[4*u+0], v4.x, acc);
            acc = fmaf(cur[4*u+1], v4.y, acc);
            acc = fmaf(cur[4*u+2], v4.z, acc);
            acc = fmaf(cur[4*u+3], v4.w, acc);
        }
        #pragma unroll
        for (int u = 0; u < 32; ++u) cur[u] = nxt[u];
    }

    // own diagonal: serial 32-col shfl chain (frozen pattern)
    float vown;
    {
        float rr = s - acc;
        #pragma unroll
        for (int m = 0; m < 32; ++m) {
            float vm = __shfl_sync(0xFFFFFFFFu, fmaxf(rr, 0.f), m);
            if (lane == m) { vsh[tid] = vm; vown = vm; }
            if (lane > m) rr = fmaf(-cur[m], vm, rr);
        }
    }
    __threadfence_block();                        // STS of vsh visible
    if (w < NCB - 1) BAR_ARRIVE(w + 1, (NCB - w) * 32);

    // ---- epilogue: E, pair constants, positive-row compaction ----
    float v = vown;
    bool valid = tid < KSEL;
    float E = valid ? __expf(20.f * v) : 0.f;
    float y = valid ? g_y[img][tid] : 0.f;
    g_E[img][tid] = E;
    g_c[img][tid] = 0.f;

    float Eb = __shfl_down_sync(0xFFFFFFFFu, E, 1);
    float yb = __shfl_down_sync(0xFFFFFFFFu, y, 1);
    if (!(lane & 1)) {
        float S = E + Eb;
        float P = E * Eb;
        float yS = fmaf(y, E, yb * Eb);
        float yP = (y + yb) * P;
        g_pair[img][tid >> 1] = make_float4(S, P, yS, yP);
    }

    bool pos = valid && (y != 0.f);
    unsigned vote = __ballot_sync(0xFFFFFFFFu, pos);
    if (lane == 0) wcnt[w] = __popc(vote);
    __syncthreads();
    int base = 0;
    #pragma unroll
    for (int ww = 0; ww < NCB; ++ww) if (ww < w) base += wcnt[ww];
    if (pos) {
        int off = __popc(vote & ((1u << lane) - 1u));
        g_rows[img][base + off] = tid;
    }
    if (tid == 0) {
        int tot = 0;
        #pragma unroll
        for (int ww = 0; ww < NCB; ++ww) tot += wcnt[ww];
        g_npos[img] = tot;
    }
}

// ---------------- K5: ap_loss — quad-column rationals, 1 rcp per 4 columns ----------------
// pair:  n = Ei*S + 2P, d = Ei^2 + Ei*S + P
// quad:  n1/d1 + n2/d2 = (n1*d2 + n2*d1) * rcp(d1*d2)   (exact; d1*d2 < 9e35)
__global__ __launch_bounds__(256) void k_ap() {
    const int img = blockIdx.y;
    const int wid = threadIdx.x >> 5, lane = threadIdx.x & 31;
    const int slot = blockIdx.x * 8 + wid;
    if (slot >= g_npos[img]) return;     // uniform per warp
    const int i = g_rows[img][slot];
    const float Ei = g_E[img][i];
    const float Ei2 = Ei * Ei;
    const float4* pr = g_pair[img];
    float sh = 0.f, shy = 0.f;
    #pragma unroll
    for (int u = 0; u < 4; ++u) {
        int t2 = (u * 32 + lane) * 2;
        float4 q1 = pr[t2];
        float4 q2 = pr[t2 + 1];
        float t1 = fmaf(Ei, q1.x, q1.y);        // Ei*S1 + P1
        float n1 = t1 + q1.y;                   // Ei*S1 + 2P1
        float d1 = Ei2 + t1;                    // Ei^2 + Ei*S1 + P1
        float ny1 = fmaf(Ei, q1.z, q1.w);       // Ei*yS1 + yP1
        float t2f = fmaf(Ei, q2.x, q2.y);
        float n2 = t2f + q2.y;
        float d2 = Ei2 + t2f;
        float ny2 = fmaf(Ei, q2.z, q2.w);
        float rr = frcp(d1 * d2);
        float num  = fmaf(n1, d2, n2 * d1);
        float numy = fmaf(ny1, d2, ny2 * d1);
        sh  = fmaf(num,  rr, sh);
        shy = fmaf(numy, rr, shy);
    }
    #pragma unroll
    for (int off = 16; off > 0; off >>= 1) {
        sh  += __shfl_down_sync(0xFFFFFFFFu, sh, off);
        shy += __shfl_down_sync(0xFFFFFFFFu, shy, off);
    }
    // sums include self-pair exactly as h_ii = 0.5
    if (lane == 0) g_c[img][i] = __fdividef(0.5f + shy, 0.5f + sh);
}

// ---------------- K6: warp-per-image final reduction ----------------
__global__ __launch_bounds__(512) void k_final(float* __restrict__ out) {
    const int w = threadIdx.x >> 5, lane = threadIdx.x & 31;
    __shared__ float part[16];
    float sc = 0.f, sy = 0.f;
    #pragma unroll
    for (int u = lane; u < KPAD; u += 32) {
        sc += g_c[w][u];
        sy += g_y[w][u];
    }
    #pragma unroll
    for (int off = 16; off > 0; off >>= 1) {
        sc += __shfl_down_sync(0xFFFFFFFFu, sc, off);
        sy += __shfl_down_sync(0xFFFFFFFFu, sy, off);
    }
    if (lane == 0) part[w] = 1.f - sc / fmaxf(sy, 1.f);
    __syncthreads();
    if (threadIdx.x == 0) {
        float t = 0.f;
        #pragma unroll
        for (int k = 0; k < NIMG; ++k) t += part[k];
        out[0] = t / (float)NIMG;
    }
}

// ---------------- driver ----------------
extern "C" void kernel_launch(void* const* d_in, const int* in_sizes, int n_in,
                              void* d_out, int out_size) {
    const float* preds = nullptr;
    const float* boxes = nullptr;
    const int*   targets = nullptr;
    for (int i = 0; i < n_in; ++i) {
        long sz = in_sizes[i];
        if (sz == (long)NIMG * NBOX * NCH) preds = (const float*)d_in[i];
        else if (sz == (long)NIMG * NBOX * 4) boxes = (const float*)d_in[i];
        else if (sz == (long)NIMG * NBOX) targets = (const int*)d_in[i];
    }
    if (!preds)   preds   = (const float*)d_in[0];
    if (!boxes)   boxes   = (const float*)d_in[1];
    if (!targets) targets = (const int*)d_in[2];

    k_scores<<<NIMG * 126, 128>>>(preds);
    k_select<<<NIMG, 512>>>(reinterpret_cast<const float4*>(boxes), targets);
    k_prune<<<dim3(34, NIMG), 128>>>();
    k_nms<<<NIMG, 512>>>();
    k_ap<<<dim3(64, NIMG), 256>>>();
    k_final<<<1, 512>>>((float*)d_out);
}